// round 5
// baseline (speedup 1.0000x reference)
#include <cuda_runtime.h>
#include <cstdint>

#define MAXN 50000
#define MAXE 800000
#define K_DIM 128

// Scratch (allocation-free rule: __device__ globals)
__device__ float  g_dinv[MAXN];
__device__ int    g_deg[MAXN];
__device__ int    g_rowptr[MAXN + 1];
__device__ int    g_cursor[MAXN];
__device__ int    g_bsum[256];
__device__ int    g_boff[256];
__device__ float2 g_csr[MAXE];         // (src as int bits, norm)
__device__ float  g_h1[(size_t)MAXN * 128];
__device__ float  g_buf1[(size_t)MAXN * 128];
__device__ float  g_h2[(size_t)MAXN * 64];

// ---------------- packed f32x2 helpers ----------------
__device__ __forceinline__ unsigned long long packdup(float x) {
    unsigned long long r;
    asm("mov.b64 %0, {%1, %1};" : "=l"(r) : "f"(x));
    return r;
}
__device__ __forceinline__ void ffma2(unsigned long long& d,
                                      unsigned long long a,
                                      unsigned long long b) {
    asm("fma.rn.f32x2 %0, %1, %2, %0;" : "+l"(d) : "l"(a), "l"(b));
}
__device__ __forceinline__ unsigned long long ffma2v(unsigned long long a,
                                                     unsigned long long b,
                                                     unsigned long long c) {
    unsigned long long d;
    asm("fma.rn.f32x2 %0, %1, %2, %3;" : "=l"(d) : "l"(a), "l"(b), "l"(c));
    return d;
}
__device__ __forceinline__ unsigned long long add2(unsigned long long a,
                                                   unsigned long long b) {
    unsigned long long d;
    asm("add.rn.f32x2 %0, %1, %2;" : "=l"(d) : "l"(a), "l"(b));
    return d;
}

// ---------------- degree / normalization / CSR build ----------------
__global__ void k_zero_deg(int n) {
    int i = blockIdx.x * blockDim.x + threadIdx.x;
    if (i < n) g_deg[i] = 0;
}

__global__ void k_count_deg(const int* __restrict__ ei, int E) {
    int i = blockIdx.x * blockDim.x + threadIdx.x;
    if (i < E) atomicAdd(&g_deg[ei[E + i]], 1);
}

// Block-level scan (+ dinv fused); exclusive within block to rowptr, block sum to bsum.
__global__ void k_scan1(int n) {
    __shared__ int s[256];
    int t = threadIdx.x;
    int i = blockIdx.x * 256 + t;
    int v = (i < n) ? g_deg[i] : 0;
    if (i < n) g_dinv[i] = rsqrtf((float)v + 1.0f);  // +1 self-loop
    s[t] = v;
    __syncthreads();
#pragma unroll
    for (int off = 1; off < 256; off <<= 1) {
        int a = (t >= off) ? s[t - off] : 0;
        __syncthreads();
        s[t] += a;
        __syncthreads();
    }
    if (i < n) g_rowptr[i] = s[t] - v;
    if (t == 255) g_bsum[blockIdx.x] = s[255];
}

__global__ void k_scan2(int nb) {
    __shared__ int s[256];
    int t = threadIdx.x;
    int v = (t < nb) ? g_bsum[t] : 0;
    s[t] = v;
    __syncthreads();
#pragma unroll
    for (int off = 1; off < 256; off <<= 1) {
        int a = (t >= off) ? s[t - off] : 0;
        __syncthreads();
        s[t] += a;
        __syncthreads();
    }
    if (t < nb) g_boff[t] = s[t] - v;
}

__global__ void k_scan3(int n) {
    int i = blockIdx.x * blockDim.x + threadIdx.x;
    if (i < n) {
        int r = g_rowptr[i] + g_boff[blockIdx.x];
        g_rowptr[i] = r;
        g_cursor[i] = r;
        if (i == n - 1) g_rowptr[n] = r + g_deg[i];
    }
}

__global__ void k_scatter(const int* __restrict__ ei, int E) {
    int e = blockIdx.x * blockDim.x + threadIdx.x;
    if (e < E) {
        int s = ei[e];
        int d = ei[E + e];
        int pos = atomicAdd(&g_cursor[d], 1);
        g_csr[pos] = make_float2(__int_as_float(s), g_dinv[s] * g_dinv[d]);
    }
}

// ---------------- GEMM: H = X @ W ; OUT = bias + H*dinv^2 ----------------
// Register-tiled: block tile 128 x NCOL, thread tile 8x8.
// X staged transposed in smem (sXT[k][row], pad 132) so per-k reads are
// 2x LDS.128 (x) + 2 or 1 LDS.128 (w). Accumulate in packed f32x2.
template <int NCOL, bool RELU>
__global__ void __launch_bounds__(NCOL * 2) k_gemm(
    const float* __restrict__ X, const float* __restrict__ W,
    const float* __restrict__ bias, const float* __restrict__ dinv,
    float* __restrict__ H, float* __restrict__ OUT, int nrows)
{
    constexpr int TX  = NCOL / 8;   // threads along cols (16 or 8)
    constexpr int T   = TX * 16;    // block threads (256 or 128)
    constexpr int R   = 128;        // rows per block
    constexpr int PAD = 132;        // sXT row pitch (floats)

    extern __shared__ float smem[];
    float* sXT = smem;                     // [K_DIM][PAD]
    float* sW  = smem + K_DIM * PAD;       // [K_DIM][NCOL]

    const int tid = threadIdx.x;
    const int tx  = tid % TX;
    const int ty  = tid / TX;
    const int row0 = blockIdx.x * R;

    // stage W (row-major, float4)
    for (int i = tid; i < K_DIM * NCOL / 4; i += T)
        ((float4*)sW)[i] = ((const float4*)W)[i];

    // stage X transposed: read float4 of (row, 4c4..), scatter to sXT[k][row]
    for (int i = tid; i < R * (K_DIM / 4); i += T) {
        int r  = i >> 5;        // local row
        int c4 = i & 31;        // float4 index along k
        float4 v = make_float4(0.f, 0.f, 0.f, 0.f);
        int row = row0 + r;
        if (row < nrows) {
            v = ((const float4*)(X + (size_t)row * K_DIM))[c4];
            if (RELU) {
                v.x = fmaxf(v.x, 0.f); v.y = fmaxf(v.y, 0.f);
                v.z = fmaxf(v.z, 0.f); v.w = fmaxf(v.w, 0.f);
            }
        }
        int k = 4 * c4;
        sXT[(k + 0) * PAD + r] = v.x;
        sXT[(k + 1) * PAD + r] = v.y;
        sXT[(k + 2) * PAD + r] = v.z;
        sXT[(k + 3) * PAD + r] = v.w;
    }
    __syncthreads();

    unsigned long long acc[8][4];
#pragma unroll
    for (int r = 0; r < 8; r++)
#pragma unroll
        for (int j = 0; j < 4; j++) acc[r][j] = 0ull;

    unsigned long long bv[4];
#pragma unroll
    for (int j = 0; j < 4; j++)
        bv[j] = *(const unsigned long long*)(bias + 8 * tx + 2 * j);

#pragma unroll 4
    for (int k = 0; k < K_DIM; k++) {
        const float* xr = sXT + k * PAD + 8 * ty;
        float4 xa = *(const float4*)(xr);
        float4 xb = *(const float4*)(xr + 4);
        const unsigned long long* wr =
            (const unsigned long long*)(sW + k * NCOL + 8 * tx);
        unsigned long long w0 = wr[0], w1 = wr[1], w2 = wr[2], w3 = wr[3];

        unsigned long long xp[8];
        xp[0] = packdup(xa.x); xp[1] = packdup(xa.y);
        xp[2] = packdup(xa.z); xp[3] = packdup(xa.w);
        xp[4] = packdup(xb.x); xp[5] = packdup(xb.y);
        xp[6] = packdup(xb.z); xp[7] = packdup(xb.w);
#pragma unroll
        for (int r = 0; r < 8; r++) {
            ffma2(acc[r][0], xp[r], w0);
            ffma2(acc[r][1], xp[r], w1);
            ffma2(acc[r][2], xp[r], w2);
            ffma2(acc[r][3], xp[r], w3);
        }
    }

#pragma unroll
    for (int rr = 0; rr < 8; rr++) {
        int row = row0 + 8 * ty + rr;
        if (row < nrows) {
            float di = dinv[row];
            unsigned long long d2 = packdup(di * di);
            unsigned long long* hp =
                (unsigned long long*)(H + (size_t)row * NCOL + 8 * tx);
            unsigned long long* op =
                (unsigned long long*)(OUT + (size_t)row * NCOL + 8 * tx);
#pragma unroll
            for (int j = 0; j < 4; j++) {
                hp[j] = acc[rr][j];
                op[j] = ffma2v(acc[rr][j], d2, bv[j]);
            }
        }
    }
}

// ---------------- CSR aggregation: OUT[n] += sum_{e in row n} H[src_e] * nrm_e ----------------
__global__ void __launch_bounds__(256) k_agg128(
    const float* __restrict__ H, float* __restrict__ OUT, int N)
{
    int gw   = (blockIdx.x * 256 + threadIdx.x) >> 5;
    int lane = threadIdx.x & 31;
    if (gw >= N) return;
    int beg = g_rowptr[gw], end = g_rowptr[gw + 1];
    if (beg == end) return;

    const float* Hl = H + lane * 4;
    unsigned long long a0 = 0ull, a1 = 0ull;

    int j = beg;
    for (; j + 2 <= end; j += 2) {
        float2 e0 = g_csr[j];
        float2 e1 = g_csr[j + 1];
        ulonglong2 v0 = *(const ulonglong2*)(Hl + (size_t)__float_as_int(e0.x) * 128);
        ulonglong2 v1 = *(const ulonglong2*)(Hl + (size_t)__float_as_int(e1.x) * 128);
        unsigned long long n0 = packdup(e0.y);
        unsigned long long n1 = packdup(e1.y);
        a0 = ffma2v(v0.x, n0, a0); a1 = ffma2v(v0.y, n0, a1);
        a0 = ffma2v(v1.x, n1, a0); a1 = ffma2v(v1.y, n1, a1);
    }
    if (j < end) {
        float2 e0 = g_csr[j];
        ulonglong2 v0 = *(const ulonglong2*)(Hl + (size_t)__float_as_int(e0.x) * 128);
        unsigned long long n0 = packdup(e0.y);
        a0 = ffma2v(v0.x, n0, a0); a1 = ffma2v(v0.y, n0, a1);
    }

    ulonglong2* op = (ulonglong2*)(OUT + (size_t)gw * 128 + lane * 4);
    ulonglong2 ob = *op;
    ob.x = add2(ob.x, a0);
    ob.y = add2(ob.y, a1);
    *op = ob;
}

__global__ void __launch_bounds__(256) k_agg64(
    const float* __restrict__ H, float* __restrict__ OUT, int N)
{
    int idx  = blockIdx.x * 256 + threadIdx.x;
    int node = idx >> 4;
    int lane = idx & 15;
    if (node >= N) return;
    int beg = g_rowptr[node], end = g_rowptr[node + 1];
    if (beg == end) return;

    const float* Hl = H + lane * 4;
    unsigned long long a0 = 0ull, a1 = 0ull;

    int j = beg;
    for (; j + 2 <= end; j += 2) {
        float2 e0 = g_csr[j];
        float2 e1 = g_csr[j + 1];
        ulonglong2 v0 = *(const ulonglong2*)(Hl + (size_t)__float_as_int(e0.x) * 64);
        ulonglong2 v1 = *(const ulonglong2*)(Hl + (size_t)__float_as_int(e1.x) * 64);
        unsigned long long n0 = packdup(e0.y);
        unsigned long long n1 = packdup(e1.y);
        a0 = ffma2v(v0.x, n0, a0); a1 = ffma2v(v0.y, n0, a1);
        a0 = ffma2v(v1.x, n1, a0); a1 = ffma2v(v1.y, n1, a1);
    }
    if (j < end) {
        float2 e0 = g_csr[j];
        ulonglong2 v0 = *(const ulonglong2*)(Hl + (size_t)__float_as_int(e0.x) * 64);
        unsigned long long n0 = packdup(e0.y);
        a0 = ffma2v(v0.x, n0, a0); a1 = ffma2v(v0.y, n0, a1);
    }

    ulonglong2* op = (ulonglong2*)(OUT + (size_t)node * 64 + lane * 4);
    ulonglong2 ob = *op;
    ob.x = add2(ob.x, a0);
    ob.y = add2(ob.y, a1);
    *op = ob;
}

// ---------------- launch ----------------
extern "C" void kernel_launch(void* const* d_in, const int* in_sizes, int n_in,
                              void* d_out, int out_size)
{
    const float* x  = (const float*)d_in[0];
    const int*   ei = (const int*)d_in[1];   // int32 edge list
    const float* W1 = (const float*)d_in[2];
    const float* b1 = (const float*)d_in[3];
    const float* W2 = (const float*)d_in[4];
    const float* b2 = (const float*)d_in[5];
    float*       out = (float*)d_out;

    const int N = in_sizes[0] / 128;   // 50000
    const int E = in_sizes[1] / 2;     // 800000

    float* dinv; cudaGetSymbolAddress((void**)&dinv, g_dinv);
    float* h1;   cudaGetSymbolAddress((void**)&h1,   g_h1);
    float* buf1; cudaGetSymbolAddress((void**)&buf1, g_buf1);
    float* h2;   cudaGetSymbolAddress((void**)&h2,   g_h2);

    const int SMEM1 = (128 * 132 + 128 * 128) * 4;  // 133120
    const int SMEM2 = (128 * 132 + 128 * 64) * 4;   // 100352
    cudaFuncSetAttribute((const void*)k_gemm<128, false>,
                         cudaFuncAttributeMaxDynamicSharedMemorySize, SMEM1);
    cudaFuncSetAttribute((const void*)k_gemm<64, true>,
                         cudaFuncAttributeMaxDynamicSharedMemorySize, SMEM2);

    const int nblkN = (N + 255) / 256;   // 196
    const int nblkE = (E + 255) / 256;

    // CSR build (counting sort by dst) + normalization
    k_zero_deg<<<nblkN, 256>>>(N);
    k_count_deg<<<nblkE, 256>>>(ei, E);
    k_scan1<<<nblkN, 256>>>(N);
    k_scan2<<<1, 256>>>(nblkN);
    k_scan3<<<nblkN, 256>>>(N);
    k_scatter<<<nblkE, 256>>>(ei, E);

    // layer 1: h1 = x@W1 ; buf1 = b1 + h1*dinv^2 (self-loop fused)
    int gblocks = (N + 127) / 128;   // 391
    k_gemm<128, false><<<gblocks, 256, SMEM1>>>(x, W1, b1, dinv, h1, buf1, N);
    k_agg128<<<(N * 32 + 255) / 256, 256>>>(h1, buf1, N);

    // layer 2: h2 = relu(buf1)@W2 ; out = b2 + h2*dinv^2
    k_gemm<64, true><<<gblocks, 128, SMEM2>>>(buf1, W2, b2, dinv, h2, out, N);
    k_agg64<<<(N * 16 + 255) / 256, 256>>>(h2, out, N);
}

// round 6
// speedup vs baseline: 1.4437x; 1.4437x over previous
#include <cuda_runtime.h>
#include <cstdint>

#define MAXN 50000
#define MAXE 800000
#define K_DIM 128

// Scratch (allocation-free rule: __device__ globals)
__device__ float  g_dinv[MAXN];
__device__ int    g_deg[MAXN];
__device__ int    g_rowptr[MAXN + 1];
__device__ int    g_cursor[MAXN];
__device__ int    g_bsum[256];
__device__ int    g_boff[256];
__device__ float2 g_csr[MAXE];         // (src as int bits, norm)
__device__ float  g_h1[(size_t)MAXN * 128];
__device__ float  g_buf1[(size_t)MAXN * 128];
__device__ float  g_h2[(size_t)MAXN * 64];

// ---------------- packed f32x2 helpers ----------------
__device__ __forceinline__ unsigned long long packdup(float x) {
    unsigned long long r;
    asm("mov.b64 %0, {%1, %1};" : "=l"(r) : "f"(x));
    return r;
}
__device__ __forceinline__ void ffma2(unsigned long long& d,
                                      unsigned long long a,
                                      unsigned long long b) {
    asm("fma.rn.f32x2 %0, %1, %2, %0;" : "+l"(d) : "l"(a), "l"(b));
}
__device__ __forceinline__ unsigned long long ffma2v(unsigned long long a,
                                                     unsigned long long b,
                                                     unsigned long long c) {
    unsigned long long d;
    asm("fma.rn.f32x2 %0, %1, %2, %3;" : "=l"(d) : "l"(a), "l"(b), "l"(c));
    return d;
}
__device__ __forceinline__ unsigned long long add2(unsigned long long a,
                                                   unsigned long long b) {
    unsigned long long d;
    asm("add.rn.f32x2 %0, %1, %2;" : "=l"(d) : "l"(a), "l"(b));
    return d;
}

// ---------------- degree / normalization / CSR build ----------------
__global__ void k_zero_deg(int n) {
    int i = blockIdx.x * blockDim.x + threadIdx.x;
    if (i < n) g_deg[i] = 0;
}

__global__ void k_count_deg(const int* __restrict__ ei, int E) {
    int i = blockIdx.x * blockDim.x + threadIdx.x;
    if (i < E) atomicAdd(&g_deg[ei[E + i]], 1);
}

// Block-level scan (+ dinv fused); exclusive within block to rowptr, block sum to bsum.
__global__ void k_scan1(int n) {
    __shared__ int s[256];
    int t = threadIdx.x;
    int i = blockIdx.x * 256 + t;
    int v = (i < n) ? g_deg[i] : 0;
    if (i < n) g_dinv[i] = rsqrtf((float)v + 1.0f);  // +1 self-loop
    s[t] = v;
    __syncthreads();
#pragma unroll
    for (int off = 1; off < 256; off <<= 1) {
        int a = (t >= off) ? s[t - off] : 0;
        __syncthreads();
        s[t] += a;
        __syncthreads();
    }
    if (i < n) g_rowptr[i] = s[t] - v;
    if (t == 255) g_bsum[blockIdx.x] = s[255];
}

__global__ void k_scan2(int nb) {
    __shared__ int s[256];
    int t = threadIdx.x;
    int v = (t < nb) ? g_bsum[t] : 0;
    s[t] = v;
    __syncthreads();
#pragma unroll
    for (int off = 1; off < 256; off <<= 1) {
        int a = (t >= off) ? s[t - off] : 0;
        __syncthreads();
        s[t] += a;
        __syncthreads();
    }
    if (t < nb) g_boff[t] = s[t] - v;
}

__global__ void k_scan3(int n) {
    int i = blockIdx.x * blockDim.x + threadIdx.x;
    if (i < n) {
        int r = g_rowptr[i] + g_boff[blockIdx.x];
        g_rowptr[i] = r;
        g_cursor[i] = r;
        if (i == n - 1) g_rowptr[n] = r + g_deg[i];
    }
}

__global__ void k_scatter(const int* __restrict__ ei, int E) {
    int e = blockIdx.x * blockDim.x + threadIdx.x;
    if (e < E) {
        int s = ei[e];
        int d = ei[E + e];
        int pos = atomicAdd(&g_cursor[d], 1);
        g_csr[pos] = make_float2(__int_as_float(s), g_dinv[s] * g_dinv[d]);
    }
}

// ---------------- GEMM: H = X @ W ; OUT = bias + H*dinv^2 ----------------
// 256 threads = 8 warps; each warp computes 8 rows x NCOL cols via packed
// fma.rn.f32x2. k chunked by 4: per chunk each row's x is ONE broadcast
// LDS.128 (4 k-values) instead of 4 scalar broadcasts -> crossbar-light.
template <int NCOL, bool RELU>
__global__ void __launch_bounds__(256, 2) k_gemm(
    const float* __restrict__ X, const float* __restrict__ W,
    const float* __restrict__ bias, const float* __restrict__ dinv,
    float* __restrict__ H, float* __restrict__ OUT, int nrows)
{
    constexpr int P = NCOL / 64;  // u64 col-pairs per lane (2 or 1)
    extern __shared__ float sW[];                  // K_DIM * NCOL
    __shared__ float sX[8][8][K_DIM];              // 32KB

    const int tid  = threadIdx.x;
    const int warp = tid >> 5;
    const int lane = tid & 31;

    const int wElems4 = K_DIM * NCOL / 4;
    for (int i = tid; i < wElems4; i += 256)
        ((float4*)sW)[i] = ((const float4*)W)[i];

    const int row0 = blockIdx.x * 64 + warp * 8;

#pragma unroll
    for (int rr = 0; rr < 8; rr++) {
        int row = row0 + rr;
        if (row < nrows) {
            float4 v = ((const float4*)(X + (size_t)row * K_DIM))[lane];
            if (RELU) {
                v.x = fmaxf(v.x, 0.0f); v.y = fmaxf(v.y, 0.0f);
                v.z = fmaxf(v.z, 0.0f); v.w = fmaxf(v.w, 0.0f);
            }
            ((float4*)&sX[warp][rr][0])[lane] = v;
        }
    }
    __syncthreads();

    unsigned long long acc[8][P];
#pragma unroll
    for (int r = 0; r < 8; r++)
#pragma unroll
        for (int j = 0; j < P; j++) acc[r][j] = 0ull;

    unsigned long long bv[P];
#pragma unroll
    for (int j = 0; j < P; j++)
        bv[j] = ((const unsigned long long*)bias)[lane * P + j];

#pragma unroll 2
    for (int k0 = 0; k0 < K_DIM; k0 += 4) {
        // W for the 4 k-steps: P x LDS.128-equivalent per k (conflict-free)
        unsigned long long w[4][P];
#pragma unroll
        for (int kk = 0; kk < 4; kk++) {
            if (P == 2) {
                ulonglong2 wv = ((const ulonglong2*)(sW + (k0 + kk) * NCOL))[lane];
                w[kk][0] = wv.x; w[kk][1] = wv.y;
            } else {
                w[kk][0] = ((const unsigned long long*)(sW + (k0 + kk) * NCOL))[lane];
            }
        }
        // x for 8 rows x 4 ks: one broadcast LDS.128 per row
        float xr[8][4];
#pragma unroll
        for (int r = 0; r < 8; r++) {
            float4 v = *(const float4*)&sX[warp][r][k0];
            xr[r][0] = v.x; xr[r][1] = v.y; xr[r][2] = v.z; xr[r][3] = v.w;
        }
#pragma unroll
        for (int kk = 0; kk < 4; kk++) {
#pragma unroll
            for (int r = 0; r < 8; r++) {
                unsigned long long xp = packdup(xr[r][kk]);
#pragma unroll
                for (int j = 0; j < P; j++) ffma2(acc[r][j], xp, w[kk][j]);
            }
        }
    }

#pragma unroll
    for (int rr = 0; rr < 8; rr++) {
        int row = row0 + rr;
        if (row < nrows) {
            float di = dinv[row];
            unsigned long long d2 = packdup(di * di);
            unsigned long long* hp = (unsigned long long*)(H   + (size_t)row * NCOL) + lane * P;
            unsigned long long* op = (unsigned long long*)(OUT + (size_t)row * NCOL) + lane * P;
#pragma unroll
            for (int j = 0; j < P; j++) {
                hp[j] = acc[rr][j];
                op[j] = ffma2v(acc[rr][j], d2, bv[j]);
            }
        }
    }
}

// ---------------- CSR aggregation: OUT[n] += sum_{e in row n} H[src_e] * nrm_e ----------------
__global__ void __launch_bounds__(256) k_agg128(
    const float* __restrict__ H, float* __restrict__ OUT, int N)
{
    int gw   = (blockIdx.x * 256 + threadIdx.x) >> 5;
    int lane = threadIdx.x & 31;
    if (gw >= N) return;
    int beg = g_rowptr[gw], end = g_rowptr[gw + 1];
    if (beg == end) return;

    const float* Hl = H + lane * 4;
    unsigned long long a0 = 0ull, a1 = 0ull;

    int j = beg;
    for (; j + 2 <= end; j += 2) {
        float2 e0 = g_csr[j];
        float2 e1 = g_csr[j + 1];
        ulonglong2 v0 = *(const ulonglong2*)(Hl + (size_t)__float_as_int(e0.x) * 128);
        ulonglong2 v1 = *(const ulonglong2*)(Hl + (size_t)__float_as_int(e1.x) * 128);
        unsigned long long n0 = packdup(e0.y);
        unsigned long long n1 = packdup(e1.y);
        a0 = ffma2v(v0.x, n0, a0); a1 = ffma2v(v0.y, n0, a1);
        a0 = ffma2v(v1.x, n1, a0); a1 = ffma2v(v1.y, n1, a1);
    }
    if (j < end) {
        float2 e0 = g_csr[j];
        ulonglong2 v0 = *(const ulonglong2*)(Hl + (size_t)__float_as_int(e0.x) * 128);
        unsigned long long n0 = packdup(e0.y);
        a0 = ffma2v(v0.x, n0, a0); a1 = ffma2v(v0.y, n0, a1);
    }

    ulonglong2* op = (ulonglong2*)(OUT + (size_t)gw * 128 + lane * 4);
    ulonglong2 ob = *op;
    ob.x = add2(ob.x, a0);
    ob.y = add2(ob.y, a1);
    *op = ob;
}

__global__ void __launch_bounds__(256) k_agg64(
    const float* __restrict__ H, float* __restrict__ OUT, int N)
{
    int idx  = blockIdx.x * 256 + threadIdx.x;
    int node = idx >> 4;
    int lane = idx & 15;
    if (node >= N) return;
    int beg = g_rowptr[node], end = g_rowptr[node + 1];
    if (beg == end) return;

    const float* Hl = H + lane * 4;
    unsigned long long a0 = 0ull, a1 = 0ull;

    int j = beg;
    for (; j + 2 <= end; j += 2) {
        float2 e0 = g_csr[j];
        float2 e1 = g_csr[j + 1];
        ulonglong2 v0 = *(const ulonglong2*)(Hl + (size_t)__float_as_int(e0.x) * 64);
        ulonglong2 v1 = *(const ulonglong2*)(Hl + (size_t)__float_as_int(e1.x) * 64);
        unsigned long long n0 = packdup(e0.y);
        unsigned long long n1 = packdup(e1.y);
        a0 = ffma2v(v0.x, n0, a0); a1 = ffma2v(v0.y, n0, a1);
        a0 = ffma2v(v1.x, n1, a0); a1 = ffma2v(v1.y, n1, a1);
    }
    if (j < end) {
        float2 e0 = g_csr[j];
        ulonglong2 v0 = *(const ulonglong2*)(Hl + (size_t)__float_as_int(e0.x) * 64);
        unsigned long long n0 = packdup(e0.y);
        a0 = ffma2v(v0.x, n0, a0); a1 = ffma2v(v0.y, n0, a1);
    }

    ulonglong2* op = (ulonglong2*)(OUT + (size_t)node * 64 + lane * 4);
    ulonglong2 ob = *op;
    ob.x = add2(ob.x, a0);
    ob.y = add2(ob.y, a1);
    *op = ob;
}

// ---------------- launch ----------------
extern "C" void kernel_launch(void* const* d_in, const int* in_sizes, int n_in,
                              void* d_out, int out_size)
{
    const float* x  = (const float*)d_in[0];
    const int*   ei = (const int*)d_in[1];   // int32 edge list
    const float* W1 = (const float*)d_in[2];
    const float* b1 = (const float*)d_in[3];
    const float* W2 = (const float*)d_in[4];
    const float* b2 = (const float*)d_in[5];
    float*       out = (float*)d_out;

    const int N = in_sizes[0] / 128;   // 50000
    const int E = in_sizes[1] / 2;     // 800000

    float* dinv; cudaGetSymbolAddress((void**)&dinv, g_dinv);
    float* h1;   cudaGetSymbolAddress((void**)&h1,   g_h1);
    float* buf1; cudaGetSymbolAddress((void**)&buf1, g_buf1);
    float* h2;   cudaGetSymbolAddress((void**)&h2,   g_h2);

    cudaFuncSetAttribute((const void*)k_gemm<128, false>,
                         cudaFuncAttributeMaxDynamicSharedMemorySize, 128 * 128 * 4);
    cudaFuncSetAttribute((const void*)k_gemm<64, true>,
                         cudaFuncAttributeMaxDynamicSharedMemorySize, 128 * 64 * 4);

    const int nblkN = (N + 255) / 256;   // 196
    const int nblkE = (E + 255) / 256;

    // CSR build (counting sort by dst) + normalization
    k_zero_deg<<<nblkN, 256>>>(N);
    k_count_deg<<<nblkE, 256>>>(ei, E);
    k_scan1<<<nblkN, 256>>>(N);
    k_scan2<<<1, 256>>>(nblkN);
    k_scan3<<<nblkN, 256>>>(N);
    k_scatter<<<nblkE, 256>>>(ei, E);

    // layer 1: h1 = x@W1 ; buf1 = b1 + h1*dinv^2 (self-loop fused)
    int gblocks = (N + 63) / 64;
    k_gemm<128, false><<<gblocks, 256, 128 * 128 * 4>>>(x, W1, b1, dinv, h1, buf1, N);
    k_agg128<<<(N * 32 + 255) / 256, 256>>>(h1, buf1, N);

    // layer 2: h2 = relu(buf1)@W2 ; out = b2 + h2*dinv^2
    k_gemm<64, true><<<gblocks, 256, 128 * 64 * 4>>>(buf1, W2, b2, dinv, h2, out, N);
    k_agg64<<<(N * 16 + 255) / 256, 256>>>(h2, out, N);
}

// round 8
// speedup vs baseline: 1.4725x; 1.0199x over previous
#include <cuda_runtime.h>
#include <cstdint>

#define MAXN 50000
#define MAXE 800000
#define K_DIM 128

// Scratch (allocation-free rule: __device__ globals)
__device__ float  g_dinv[MAXN];
__device__ int    g_deg[MAXN];
__device__ int    g_rowptr[MAXN + 1];
__device__ int    g_cursor[MAXN];
__device__ int    g_bsum[256];
__device__ int    g_boff[256];
__device__ int    g_arrive;
__device__ int    g_flag;
__device__ float2 g_csr[MAXE];         // (src as int bits, norm)
__device__ float  g_h1[(size_t)MAXN * 128];
__device__ float  g_buf1[(size_t)MAXN * 128];
__device__ float  g_h2[(size_t)MAXN * 64];

// ---------------- packed f32x2 helpers ----------------
__device__ __forceinline__ unsigned long long packdup(float x) {
    unsigned long long r;
    asm("mov.b64 %0, {%1, %1};" : "=l"(r) : "f"(x));
    return r;
}
__device__ __forceinline__ void ffma2(unsigned long long& d,
                                      unsigned long long a,
                                      unsigned long long b) {
    asm("fma.rn.f32x2 %0, %1, %2, %0;" : "+l"(d) : "l"(a), "l"(b));
}
__device__ __forceinline__ unsigned long long ffma2v(unsigned long long a,
                                                     unsigned long long b,
                                                     unsigned long long c) {
    unsigned long long d;
    asm("fma.rn.f32x2 %0, %1, %2, %3;" : "=l"(d) : "l"(a), "l"(b), "l"(c));
    return d;
}
__device__ __forceinline__ unsigned long long add2(unsigned long long a,
                                                   unsigned long long b) {
    unsigned long long d;
    asm("add.rn.f32x2 %0, %1, %2;" : "=l"(d) : "l"(a), "l"(b));
    return d;
}

// ---------------- degree / CSR build ----------------
__global__ void k_zero_deg(int n) {
    int i = blockIdx.x * blockDim.x + threadIdx.x;
    if (i < n) g_deg[i] = 0;
    if (i == 0) { g_arrive = 0; g_flag = 0; }   // reset single-pass scan state
}

__global__ void k_count_deg(const int* __restrict__ ei, int E) {
    int i = blockIdx.x * blockDim.x + threadIdx.x;
    if (i < E) atomicAdd(&g_deg[ei[E + i]], 1);
}

// Single-pass scan: per-block scan + dinv, last-arriving block scans block sums,
// all blocks then add their offset. nb must be <= 256 and all blocks co-resident
// (196 blocks, 8 blocks/SM thread-limit -> 1184 slots on 148 SMs).
__global__ void __launch_bounds__(256) k_scan_all(int n, int nb) {
    __shared__ int s[256];
    __shared__ int s_go;
    int t = threadIdx.x, b = blockIdx.x;
    int i = b * 256 + t;
    int v = (i < n) ? g_deg[i] : 0;
    if (i < n) g_dinv[i] = rsqrtf((float)v + 1.0f);  // +1 self-loop

    s[t] = v;
    __syncthreads();
#pragma unroll
    for (int off = 1; off < 256; off <<= 1) {
        int a = (t >= off) ? s[t - off] : 0;
        __syncthreads();
        s[t] += a;
        __syncthreads();
    }
    int incl = s[t];

    if (t == 255) {
        g_bsum[b] = incl;
        __threadfence();
        int tk = atomicAdd(&g_arrive, 1);
        s_go = (tk == nb - 1);
    }
    __syncthreads();

    if (s_go) {
        // last-arriving block: exclusive-scan the block sums
        int bv2 = (t < nb) ? g_bsum[t] : 0;
        s[t] = bv2;
        __syncthreads();
#pragma unroll
        for (int off = 1; off < 256; off <<= 1) {
            int a = (t >= off) ? s[t - off] : 0;
            __syncthreads();
            s[t] += a;
            __syncthreads();
        }
        if (t < nb) g_boff[t] = s[t] - bv2;
        __threadfence();
        if (t == 0) atomicExch(&g_flag, 1);
    } else {
        if (t == 0) { while (atomicAdd(&g_flag, 0) == 0) { } }
        __syncthreads();
    }

    int boff = *((volatile int*)&g_boff[b]);
    if (i < n) {
        int r = incl - v + boff;     // global exclusive prefix
        g_rowptr[i] = r;
        g_cursor[i] = r;
        if (i == n - 1) g_rowptr[n] = r + v;
    }
}

__global__ void k_scatter(const int* __restrict__ ei, int E) {
    int e = blockIdx.x * blockDim.x + threadIdx.x;
    if (e < E) {
        int s = ei[e];
        int d = ei[E + e];
        int pos = atomicAdd(&g_cursor[d], 1);
        g_csr[pos] = make_float2(__int_as_float(s), g_dinv[s] * g_dinv[d]);
    }
}

// ---------------- GEMM: H = X @ W ; OUT = bias + H*dinv^2 ----------------
// 256 threads = 8 warps; each warp computes 8 rows x NCOL cols via packed
// fma.rn.f32x2. W staged in TWO K-phases of 64 (sW = 64*NCOL floats) to halve
// smem -> 3 blocks/SM (24 warps) for latency hiding.
template <int NCOL, bool RELU>
__global__ void __launch_bounds__(256, 3) k_gemm(
    const float* __restrict__ X, const float* __restrict__ W,
    const float* __restrict__ bias, const float* __restrict__ dinv,
    float* __restrict__ H, float* __restrict__ OUT, int nrows)
{
    constexpr int P = NCOL / 64;  // u64 col-pairs per lane (2 or 1)
    extern __shared__ float sW[];                  // 64 * NCOL
    __shared__ float sX[8][8][K_DIM];              // 32KB

    const int tid  = threadIdx.x;
    const int warp = tid >> 5;
    const int lane = tid & 31;

    const int row0 = blockIdx.x * 64 + warp * 8;

#pragma unroll
    for (int rr = 0; rr < 8; rr++) {
        int row = row0 + rr;
        if (row < nrows) {
            float4 v = ((const float4*)(X + (size_t)row * K_DIM))[lane];
            if (RELU) {
                v.x = fmaxf(v.x, 0.0f); v.y = fmaxf(v.y, 0.0f);
                v.z = fmaxf(v.z, 0.0f); v.w = fmaxf(v.w, 0.0f);
            }
            ((float4*)&sX[warp][rr][0])[lane] = v;
        }
    }

    unsigned long long acc[8][P];
#pragma unroll
    for (int r = 0; r < 8; r++)
#pragma unroll
        for (int j = 0; j < P; j++) acc[r][j] = 0ull;

    unsigned long long bv[P];
#pragma unroll
    for (int j = 0; j < P; j++)
        bv[j] = ((const unsigned long long*)bias)[lane * P + j];

#pragma unroll
    for (int ph = 0; ph < 2; ph++) {
        __syncthreads();   // covers X staging (ph0) and sW reuse (ph1)
        const float* Wp = W + ph * (64 * NCOL);
        for (int i = tid; i < 64 * NCOL / 4; i += 256)
            ((float4*)sW)[i] = ((const float4*)Wp)[i];
        __syncthreads();

        const int kb = ph * 64;
#pragma unroll 4
        for (int k0 = 0; k0 < 64; k0 += 2) {
            unsigned long long w[2][P];
#pragma unroll
            for (int kk = 0; kk < 2; kk++) {
                if (P == 2) {
                    ulonglong2 wv = ((const ulonglong2*)(sW + (k0 + kk) * NCOL))[lane];
                    w[kk][0] = wv.x; w[kk][1] = wv.y;
                } else {
                    w[kk][0] = ((const unsigned long long*)(sW + (k0 + kk) * NCOL))[lane];
                }
            }
            float2 xr[8];
#pragma unroll
            for (int r = 0; r < 8; r++)
                xr[r] = *(const float2*)&sX[warp][r][kb + k0];
#pragma unroll
            for (int r = 0; r < 8; r++) {
                unsigned long long xp0 = packdup(xr[r].x);
                unsigned long long xp1 = packdup(xr[r].y);
#pragma unroll
                for (int j = 0; j < P; j++) {
                    ffma2(acc[r][j], xp0, w[0][j]);
                    ffma2(acc[r][j], xp1, w[1][j]);
                }
            }
        }
    }

#pragma unroll
    for (int rr = 0; rr < 8; rr++) {
        int row = row0 + rr;
        if (row < nrows) {
            float di = dinv[row];
            unsigned long long d2 = packdup(di * di);
            unsigned long long* hp = (unsigned long long*)(H   + (size_t)row * NCOL) + lane * P;
            unsigned long long* op = (unsigned long long*)(OUT + (size_t)row * NCOL) + lane * P;
#pragma unroll
            for (int j = 0; j < P; j++) {
                hp[j] = acc[rr][j];
                op[j] = ffma2v(acc[rr][j], d2, bv[j]);
            }
        }
    }
}

// ---------------- CSR aggregation: OUT[n] += sum_{e in row n} H[src_e] * nrm_e ----------------
__global__ void __launch_bounds__(256) k_agg128(
    const float* __restrict__ H, float* __restrict__ OUT, int N)
{
    int gw   = (blockIdx.x * 256 + threadIdx.x) >> 5;
    int lane = threadIdx.x & 31;
    if (gw >= N) return;
    int beg = g_rowptr[gw], end = g_rowptr[gw + 1];
    if (beg == end) return;

    const float* Hl = H + lane * 4;
    unsigned long long a0 = 0ull, a1 = 0ull;

    int j = beg;
    for (; j + 2 <= end; j += 2) {
        float2 e0 = g_csr[j];
        float2 e1 = g_csr[j + 1];
        ulonglong2 v0 = *(const ulonglong2*)(Hl + (size_t)__float_as_int(e0.x) * 128);
        ulonglong2 v1 = *(const ulonglong2*)(Hl + (size_t)__float_as_int(e1.x) * 128);
        unsigned long long n0 = packdup(e0.y);
        unsigned long long n1 = packdup(e1.y);
        a0 = ffma2v(v0.x, n0, a0); a1 = ffma2v(v0.y, n0, a1);
        a0 = ffma2v(v1.x, n1, a0); a1 = ffma2v(v1.y, n1, a1);
    }
    if (j < end) {
        float2 e0 = g_csr[j];
        ulonglong2 v0 = *(const ulonglong2*)(Hl + (size_t)__float_as_int(e0.x) * 128);
        unsigned long long n0 = packdup(e0.y);
        a0 = ffma2v(v0.x, n0, a0); a1 = ffma2v(v0.y, n0, a1);
    }

    ulonglong2* op = (ulonglong2*)(OUT + (size_t)gw * 128 + lane * 4);
    ulonglong2 ob = *op;
    ob.x = add2(ob.x, a0);
    ob.y = add2(ob.y, a1);
    *op = ob;
}

__global__ void __launch_bounds__(256) k_agg64(
    const float* __restrict__ H, float* __restrict__ OUT, int N)
{
    int idx  = blockIdx.x * 256 + threadIdx.x;
    int node = idx >> 4;
    int lane = idx & 15;
    if (node >= N) return;
    int beg = g_rowptr[node], end = g_rowptr[node + 1];
    if (beg == end) return;

    const float* Hl = H + lane * 4;
    unsigned long long a0 = 0ull, a1 = 0ull;

    int j = beg;
    for (; j + 2 <= end; j += 2) {
        float2 e0 = g_csr[j];
        float2 e1 = g_csr[j + 1];
        ulonglong2 v0 = *(const ulonglong2*)(Hl + (size_t)__float_as_int(e0.x) * 64);
        ulonglong2 v1 = *(const ulonglong2*)(Hl + (size_t)__float_as_int(e1.x) * 64);
        unsigned long long n0 = packdup(e0.y);
        unsigned long long n1 = packdup(e1.y);
        a0 = ffma2v(v0.x, n0, a0); a1 = ffma2v(v0.y, n0, a1);
        a0 = ffma2v(v1.x, n1, a0); a1 = ffma2v(v1.y, n1, a1);
    }
    if (j < end) {
        float2 e0 = g_csr[j];
        ulonglong2 v0 = *(const ulonglong2*)(Hl + (size_t)__float_as_int(e0.x) * 64);
        unsigned long long n0 = packdup(e0.y);
        a0 = ffma2v(v0.x, n0, a0); a1 = ffma2v(v0.y, n0, a1);
    }

    ulonglong2* op = (ulonglong2*)(OUT + (size_t)node * 64 + lane * 4);
    ulonglong2 ob = *op;
    ob.x = add2(ob.x, a0);
    ob.y = add2(ob.y, a1);
    *op = ob;
}

// ---------------- launch ----------------
extern "C" void kernel_launch(void* const* d_in, const int* in_sizes, int n_in,
                              void* d_out, int out_size)
{
    const float* x  = (const float*)d_in[0];
    const int*   ei = (const int*)d_in[1];   // int32 edge list
    const float* W1 = (const float*)d_in[2];
    const float* b1 = (const float*)d_in[3];
    const float* W2 = (const float*)d_in[4];
    const float* b2 = (const float*)d_in[5];
    float*       out = (float*)d_out;

    const int N = in_sizes[0] / 128;   // 50000
    const int E = in_sizes[1] / 2;     // 800000

    float* dinv; cudaGetSymbolAddress((void**)&dinv, g_dinv);
    float* h1;   cudaGetSymbolAddress((void**)&h1,   g_h1);
    float* buf1; cudaGetSymbolAddress((void**)&buf1, g_buf1);
    float* h2;   cudaGetSymbolAddress((void**)&h2,   g_h2);

    // static sX (32KB) + dynamic sW counts against the combined 48KB default:
    // MUST raise the dynamic limit even though dynamic alone is < 48KB.
    cudaFuncSetAttribute((const void*)k_gemm<128, false>,
                         cudaFuncAttributeMaxDynamicSharedMemorySize, 64 * 128 * 4);
    cudaFuncSetAttribute((const void*)k_gemm<64, true>,
                         cudaFuncAttributeMaxDynamicSharedMemorySize, 64 * 64 * 4);

    const int nblkN = (N + 255) / 256;   // 196 (<= 256 required by k_scan_all)
    const int nblkE = (E + 255) / 256;

    // CSR build (counting sort by dst) + normalization
    k_zero_deg<<<nblkN, 256>>>(N);
    k_count_deg<<<nblkE, 256>>>(ei, E);
    k_scan_all<<<nblkN, 256>>>(N, nblkN);
    k_scatter<<<nblkE, 256>>>(ei, E);

    // layer 1: h1 = x@W1 ; buf1 = b1 + h1*dinv^2 (self-loop fused)
    int gblocks = (N + 63) / 64;
    k_gemm<128, false><<<gblocks, 256, 64 * 128 * 4>>>(x, W1, b1, dinv, h1, buf1, N);
    k_agg128<<<(N * 32 + 255) / 256, 256>>>(h1, buf1, N);

    // layer 2: h2 = relu(buf1)@W2 ; out = b2 + h2*dinv^2
    k_gemm<64, true><<<gblocks, 256, 64 * 64 * 4>>>(buf1, W2, b2, dinv, h2, out, N);
    k_agg64<<<(N * 16 + 255) / 256, 256>>>(h2, out, N);
}

// round 10
// speedup vs baseline: 1.6741x; 1.1369x over previous
#include <cuda_runtime.h>
#include <cuda_bf16.h>
#include <cstdint>

#define MAXN 50000
#define MAXE 800000
#define K_DIM 128

// ---------------- scratch (__device__ globals; no allocs allowed) ----------------
__device__ float  g_dinv[MAXN];
__device__ int    g_deg[MAXN];
__device__ int    g_rowptr[MAXN + 1];
__device__ int    g_cursor[MAXN];
__device__ int    g_bsum[256];
__device__ int    g_boff[256];
__device__ int    g_arrive;
__device__ int    g_flag;
__device__ float2 g_csr[MAXE];
__device__ float  g_h1[(size_t)MAXN * 128];
__device__ float  g_buf1[(size_t)MAXN * 128];
__device__ float  g_h2[(size_t)MAXN * 64];
// bf16 split weights, plain row-major [k][n]
__device__ uint16_t g_w1h[128 * 128], g_w1l[128 * 128];
__device__ uint16_t g_w2h[128 * 64],  g_w2l[128 * 64];

// ---------------- packed f32x2 helpers (agg path) ----------------
__device__ __forceinline__ unsigned long long packdup(float x) {
    unsigned long long r;
    asm("mov.b64 %0, {%1, %1};" : "=l"(r) : "f"(x));
    return r;
}
__device__ __forceinline__ unsigned long long ffma2v(unsigned long long a,
                                                     unsigned long long b,
                                                     unsigned long long c) {
    unsigned long long d;
    asm("fma.rn.f32x2 %0, %1, %2, %3;" : "=l"(d) : "l"(a), "l"(b), "l"(c));
    return d;
}
__device__ __forceinline__ unsigned long long add2(unsigned long long a,
                                                   unsigned long long b) {
    unsigned long long d;
    asm("add.rn.f32x2 %0, %1, %2;" : "=l"(d) : "l"(a), "l"(b));
    return d;
}

// ---------------- mma / ldmatrix helpers (sm_80-era, valid at compute_103) ----------------
__device__ __forceinline__ uint32_t smem_u32(const void* p) {
    uint32_t a;
    asm("{ .reg .u64 t; cvta.to.shared.u64 t, %1; cvt.u32.u64 %0, t; }"
        : "=r"(a) : "l"(p));
    return a;
}
__device__ __forceinline__ void mma16816(float* d, const uint32_t* a, const uint32_t* b) {
    asm volatile(
        "mma.sync.aligned.m16n8k16.row.col.f32.bf16.bf16.f32 "
        "{%0,%1,%2,%3}, {%4,%5,%6,%7}, {%8,%9}, {%0,%1,%2,%3};"
        : "+f"(d[0]), "+f"(d[1]), "+f"(d[2]), "+f"(d[3])
        : "r"(a[0]), "r"(a[1]), "r"(a[2]), "r"(a[3]), "r"(b[0]), "r"(b[1]));
}
__device__ __forceinline__ void ldsm_x4(uint32_t* r, uint32_t addr) {
    asm volatile("ldmatrix.sync.aligned.m8n8.x4.shared.b16 {%0,%1,%2,%3}, [%4];"
                 : "=r"(r[0]), "=r"(r[1]), "=r"(r[2]), "=r"(r[3]) : "r"(addr));
}
__device__ __forceinline__ void ldsm_x4t(uint32_t* r, uint32_t addr) {
    asm volatile("ldmatrix.sync.aligned.m8n8.x4.trans.shared.b16 {%0,%1,%2,%3}, [%4];"
                 : "=r"(r[0]), "=r"(r[1]), "=r"(r[2]), "=r"(r[3]) : "r"(addr));
}
__device__ __forceinline__ void split_bf16(float x, uint16_t& hi, uint16_t& lo) {
    __nv_bfloat16 h = __float2bfloat16_rn(x);
    __nv_bfloat16 l = __float2bfloat16_rn(x - __bfloat162float(h));
    hi = __bfloat16_as_ushort(h);
    lo = __bfloat16_as_ushort(l);
}

// ---------------- weight split (once per call) ----------------
__global__ void k_convW_all(const float* __restrict__ W1, const float* __restrict__ W2) {
    int idx = blockIdx.x * blockDim.x + threadIdx.x;
    if (idx < 128 * 128) {
        uint16_t h, l;
        split_bf16(W1[idx], h, l);
        g_w1h[idx] = h; g_w1l[idx] = l;
    } else if (idx < 128 * 128 + 128 * 64) {
        int j = idx - 128 * 128;
        uint16_t h, l;
        split_bf16(W2[j], h, l);
        g_w2h[j] = h; g_w2l[j] = l;
    }
}

// ---------------- degree / CSR build ----------------
__global__ void k_zero_deg(int n) {
    int i = blockIdx.x * blockDim.x + threadIdx.x;
    if (i < n) g_deg[i] = 0;
    if (i == 0) { g_arrive = 0; g_flag = 0; }
}

__global__ void k_count_deg(const int* __restrict__ ei, int E) {
    int i = blockIdx.x * blockDim.x + threadIdx.x;
    if (i < E) atomicAdd(&g_deg[ei[E + i]], 1);
}

__global__ void __launch_bounds__(256) k_scan_all(int n, int nb) {
    __shared__ int s[256];
    __shared__ int s_go;
    int t = threadIdx.x, b = blockIdx.x;
    int i = b * 256 + t;
    int v = (i < n) ? g_deg[i] : 0;
    if (i < n) g_dinv[i] = rsqrtf((float)v + 1.0f);
    s[t] = v;
    __syncthreads();
#pragma unroll
    for (int off = 1; off < 256; off <<= 1) {
        int a = (t >= off) ? s[t - off] : 0;
        __syncthreads();
        s[t] += a;
        __syncthreads();
    }
    int incl = s[t];
    if (t == 255) {
        g_bsum[b] = incl;
        __threadfence();
        int tk = atomicAdd(&g_arrive, 1);
        s_go = (tk == nb - 1);
    }
    __syncthreads();
    if (s_go) {
        int bv2 = (t < nb) ? g_bsum[t] : 0;
        s[t] = bv2;
        __syncthreads();
#pragma unroll
        for (int off = 1; off < 256; off <<= 1) {
            int a = (t >= off) ? s[t - off] : 0;
            __syncthreads();
            s[t] += a;
            __syncthreads();
        }
        if (t < nb) g_boff[t] = s[t] - bv2;
        __threadfence();
        if (t == 0) atomicExch(&g_flag, 1);
    } else {
        if (t == 0) { while (atomicAdd(&g_flag, 0) == 0) { } }
        __syncthreads();
    }
    int boff = *((volatile int*)&g_boff[b]);
    if (i < n) {
        int r = incl - v + boff;
        g_rowptr[i] = r;
        g_cursor[i] = r;
        if (i == n - 1) g_rowptr[n] = r + v;
    }
}

__global__ void k_scatter(const int* __restrict__ ei, int E) {
    int e = blockIdx.x * blockDim.x + threadIdx.x;
    if (e < E) {
        int s = ei[e];
        int d = ei[E + e];
        int pos = atomicAdd(&g_cursor[d], 1);
        g_csr[pos] = make_float2(__int_as_float(s), g_dinv[s] * g_dinv[d]);
    }
}

// ---------------- tensor-core GEMM: H = X @ W ; OUT = bias + H*dinv^2 ----------------
// 256 threads = 8 warps; block tile 128 rows; each warp: 16 rows x NCOL cols.
// 3xBF16 split (hi*hi + hi*lo + lo*hi), fp32 accumulate via mma.sync m16n8k16.
template <int NCOL, bool RELU>
__global__ void __launch_bounds__(256, 1) k_gemm_mma(
    const float* __restrict__ X, const float* __restrict__ bias,
    const float* __restrict__ dinv, float* __restrict__ H,
    float* __restrict__ OUT, int nrows)
{
    constexpr int PX = 136;                        // X pitch (bf16); 272B = 17 chunks
    constexpr int PW = (NCOL == 128) ? 136 : 72;   // W pitch; 272B/144B, conflict-free
    constexpr int NT = NCOL / 8;                   // n-tiles per warp

    extern __shared__ uint16_t sm16[];
    uint16_t* sXh = sm16;
    uint16_t* sXl = sXh + 128 * PX;
    uint16_t* sWh = sXl + 128 * PX;
    uint16_t* sWl = sWh + 128 * PW;

    const int tid  = threadIdx.x;
    const int warp = tid >> 5;
    const int lane = tid & 31;
    const int row0 = blockIdx.x * 128;

    // stage W from pre-split global bf16 [128][NCOL] into padded smem
    {
        const uint4* gh = (const uint4*)((NCOL == 128) ? g_w1h : g_w2h);
        const uint4* gl = (const uint4*)((NCOL == 128) ? g_w1l : g_w2l);
        for (int i = tid; i < 128 * (NCOL / 8); i += 256) {
            int k = i / (NCOL / 8), c = i % (NCOL / 8);
            ((uint4*)(sWh + k * PW))[c] = gh[i];
            ((uint4*)(sWl + k * PW))[c] = gl[i];
        }
    }

    // stage X: thread handles row tid/2, 64-col half tid&1; split to bf16 hi/lo
    {
        int r = tid >> 1, half = tid & 1;
        int row = row0 + r;
        uint32_t* dh = (uint32_t*)(sXh + r * PX + half * 64);
        uint32_t* dl = (uint32_t*)(sXl + r * PX + half * 64);
        if (row < nrows) {
            const float4* xr = (const float4*)(X + (size_t)row * K_DIM) + half * 16;
#pragma unroll 4
            for (int c4 = 0; c4 < 16; c4++) {
                float4 v = xr[c4];
                if (RELU) {
                    v.x = fmaxf(v.x, 0.f); v.y = fmaxf(v.y, 0.f);
                    v.z = fmaxf(v.z, 0.f); v.w = fmaxf(v.w, 0.f);
                }
                uint16_t h0, l0, h1, l1, h2, l2, h3, l3;
                split_bf16(v.x, h0, l0); split_bf16(v.y, h1, l1);
                split_bf16(v.z, h2, l2); split_bf16(v.w, h3, l3);
                dh[2 * c4]     = (uint32_t)h0 | ((uint32_t)h1 << 16);
                dh[2 * c4 + 1] = (uint32_t)h2 | ((uint32_t)h3 << 16);
                dl[2 * c4]     = (uint32_t)l0 | ((uint32_t)l1 << 16);
                dl[2 * c4 + 1] = (uint32_t)l2 | ((uint32_t)l3 << 16);
            }
        } else {
#pragma unroll 4
            for (int c4 = 0; c4 < 16; c4++) {
                dh[2 * c4] = 0u; dh[2 * c4 + 1] = 0u;
                dl[2 * c4] = 0u; dl[2 * c4 + 1] = 0u;
            }
        }
    }
    __syncthreads();

    const uint32_t bXh = smem_u32(sXh), bXl = smem_u32(sXl);
    const uint32_t bWh = smem_u32(sWh), bWl = smem_u32(sWl);

    float acc[NT][4];
#pragma unroll
    for (int j = 0; j < NT; j++) {
        acc[j][0] = 0.f; acc[j][1] = 0.f; acc[j][2] = 0.f; acc[j][3] = 0.f;
    }

    const int mrow = warp * 16;
    const uint32_t aoff = ((uint32_t)(mrow + (lane & 15)) * PX + ((lane >> 4) << 3)) * 2;
    const uint32_t boff = ((uint32_t)(lane & 15) * PW + ((lane >> 4) << 3)) * 2;

#pragma unroll
    for (int kt = 0; kt < 8; kt++) {
        uint32_t ah[4], al[4];
        ldsm_x4(ah, bXh + aoff + kt * 32);              // +16 bf16 cols per kt
        ldsm_x4(al, bXl + aoff + kt * 32);
        uint32_t bk = kt * 16 * PW * 2;                 // +16 k-rows per kt
#pragma unroll
        for (int np = 0; np < NT / 2; np++) {
            uint32_t bh[4], bl[4];
            ldsm_x4t(bh, bWh + boff + bk + np * 32);    // 2 n-tiles per ldmatrix
            ldsm_x4t(bl, bWl + boff + bk + np * 32);
            mma16816(acc[2 * np],     ah, bh);
            mma16816(acc[2 * np + 1], ah, bh + 2);
            mma16816(acc[2 * np],     ah, bl);
            mma16816(acc[2 * np + 1], ah, bl + 2);
            mma16816(acc[2 * np],     al, bh);
            mma16816(acc[2 * np + 1], al, bh + 2);
        }
    }

    // epilogue: thread owns rows (mrow + lane/4) and +8, col pairs (lane%4)*2 per ntile
    {
        int r0g = row0 + mrow + (lane >> 2);
        int r1g = r0g + 8;
        float d20 = 0.f, d21 = 0.f;
        if (r0g < nrows) { float di = dinv[r0g]; d20 = di * di; }
        if (r1g < nrows) { float di = dinv[r1g]; d21 = di * di; }
#pragma unroll
        for (int j = 0; j < NT; j++) {
            int col = j * 8 + (lane & 3) * 2;
            float2 bb = *(const float2*)(bias + col);
            if (r0g < nrows) {
                *(float2*)(H + (size_t)r0g * NCOL + col) =
                    make_float2(acc[j][0], acc[j][1]);
                *(float2*)(OUT + (size_t)r0g * NCOL + col) =
                    make_float2(fmaf(acc[j][0], d20, bb.x), fmaf(acc[j][1], d20, bb.y));
            }
            if (r1g < nrows) {
                *(float2*)(H + (size_t)r1g * NCOL + col) =
                    make_float2(acc[j][2], acc[j][3]);
                *(float2*)(OUT + (size_t)r1g * NCOL + col) =
                    make_float2(fmaf(acc[j][2], d21, bb.x), fmaf(acc[j][3], d21, bb.y));
            }
        }
    }
}

// ---------------- CSR aggregation (unchanged, known good) ----------------
__global__ void __launch_bounds__(256) k_agg128(
    const float* __restrict__ H, float* __restrict__ OUT, int N)
{
    int gw   = (blockIdx.x * 256 + threadIdx.x) >> 5;
    int lane = threadIdx.x & 31;
    if (gw >= N) return;
    int beg = g_rowptr[gw], end = g_rowptr[gw + 1];
    if (beg == end) return;

    const float* Hl = H + lane * 4;
    unsigned long long a0 = 0ull, a1 = 0ull;
    int j = beg;
    for (; j + 2 <= end; j += 2) {
        float2 e0 = g_csr[j];
        float2 e1 = g_csr[j + 1];
        ulonglong2 v0 = *(const ulonglong2*)(Hl + (size_t)__float_as_int(e0.x) * 128);
        ulonglong2 v1 = *(const ulonglong2*)(Hl + (size_t)__float_as_int(e1.x) * 128);
        unsigned long long n0 = packdup(e0.y);
        unsigned long long n1 = packdup(e1.y);
        a0 = ffma2v(v0.x, n0, a0); a1 = ffma2v(v0.y, n0, a1);
        a0 = ffma2v(v1.x, n1, a0); a1 = ffma2v(v1.y, n1, a1);
    }
    if (j < end) {
        float2 e0 = g_csr[j];
        ulonglong2 v0 = *(const ulonglong2*)(Hl + (size_t)__float_as_int(e0.x) * 128);
        unsigned long long n0 = packdup(e0.y);
        a0 = ffma2v(v0.x, n0, a0); a1 = ffma2v(v0.y, n0, a1);
    }
    ulonglong2* op = (ulonglong2*)(OUT + (size_t)gw * 128 + lane * 4);
    ulonglong2 ob = *op;
    ob.x = add2(ob.x, a0);
    ob.y = add2(ob.y, a1);
    *op = ob;
}

__global__ void __launch_bounds__(256) k_agg64(
    const float* __restrict__ H, float* __restrict__ OUT, int N)
{
    int idx  = blockIdx.x * 256 + threadIdx.x;
    int node = idx >> 4;
    int lane = idx & 15;
    if (node >= N) return;
    int beg = g_rowptr[node], end = g_rowptr[node + 1];
    if (beg == end) return;

    const float* Hl = H + lane * 4;
    unsigned long long a0 = 0ull, a1 = 0ull;
    int j = beg;
    for (; j + 2 <= end; j += 2) {
        float2 e0 = g_csr[j];
        float2 e1 = g_csr[j + 1];
        ulonglong2 v0 = *(const ulonglong2*)(Hl + (size_t)__float_as_int(e0.x) * 64);
        ulonglong2 v1 = *(const ulonglong2*)(Hl + (size_t)__float_as_int(e1.x) * 64);
        unsigned long long n0 = packdup(e0.y);
        unsigned long long n1 = packdup(e1.y);
        a0 = ffma2v(v0.x, n0, a0); a1 = ffma2v(v0.y, n0, a1);
        a0 = ffma2v(v1.x, n1, a0); a1 = ffma2v(v1.y, n1, a1);
    }
    if (j < end) {
        float2 e0 = g_csr[j];
        ulonglong2 v0 = *(const ulonglong2*)(Hl + (size_t)__float_as_int(e0.x) * 64);
        unsigned long long n0 = packdup(e0.y);
        a0 = ffma2v(v0.x, n0, a0); a1 = ffma2v(v0.y, n0, a1);
    }
    ulonglong2* op = (ulonglong2*)(OUT + (size_t)node * 64 + lane * 4);
    ulonglong2 ob = *op;
    ob.x = add2(ob.x, a0);
    ob.y = add2(ob.y, a1);
    *op = ob;
}

// ---------------- launch ----------------
extern "C" void kernel_launch(void* const* d_in, const int* in_sizes, int n_in,
                              void* d_out, int out_size)
{
    const float* x  = (const float*)d_in[0];
    const int*   ei = (const int*)d_in[1];
    const float* W1 = (const float*)d_in[2];
    const float* b1 = (const float*)d_in[3];
    const float* W2 = (const float*)d_in[4];
    const float* b2 = (const float*)d_in[5];
    float*       out = (float*)d_out;

    const int N = in_sizes[0] / 128;   // 50000
    const int E = in_sizes[1] / 2;     // 800000

    float* dinv; cudaGetSymbolAddress((void**)&dinv, g_dinv);
    float* h1;   cudaGetSymbolAddress((void**)&h1,   g_h1);
    float* buf1; cudaGetSymbolAddress((void**)&buf1, g_buf1);
    float* h2;   cudaGetSymbolAddress((void**)&h2,   g_h2);

    const int SM1 = (2 * 128 * 136 + 2 * 128 * 136) * 2;  // 139264
    const int SM2 = (2 * 128 * 136 + 2 * 128 * 72) * 2;   // 106496
    cudaFuncSetAttribute((const void*)k_gemm_mma<128, false>,
                         cudaFuncAttributeMaxDynamicSharedMemorySize, SM1);
    cudaFuncSetAttribute((const void*)k_gemm_mma<64, true>,
                         cudaFuncAttributeMaxDynamicSharedMemorySize, SM2);

    const int nblkN = (N + 255) / 256;
    const int nblkE = (E + 255) / 256;

    // weight bf16 split (once per call)
    k_convW_all<<<(128 * 128 + 128 * 64 + 255) / 256, 256>>>(W1, W2);

    // CSR build
    k_zero_deg<<<nblkN, 256>>>(N);
    k_count_deg<<<nblkE, 256>>>(ei, E);
    k_scan_all<<<nblkN, 256>>>(N, nblkN);
    k_scatter<<<nblkE, 256>>>(ei, E);

    // layer 1: h1 = x@W1 ; buf1 = b1 + h1*dinv^2 (self-loop fused)
    int gblocks = (N + 127) / 128;   // 391
    k_gemm_mma<128, false><<<gblocks, 256, SM1>>>(x, b1, dinv, h1, buf1, N);
    k_agg128<<<(N * 32 + 255) / 256, 256>>>(h1, buf1, N);

    // layer 2: h2 = relu(buf1)@W2 ; out = b2 + h2*dinv^2
    k_gemm_mma<64, true><<<gblocks, 256, SM2>>>(buf1, b2, dinv, h2, out, N);
    k_agg64<<<(N * 16 + 255) / 256, 256>>>(h2, out, N);
}

// round 11
// speedup vs baseline: 1.8123x; 1.0825x over previous
#include <cuda_runtime.h>
#include <cuda_bf16.h>
#include <cuda_fp16.h>
#include <cstdint>

#define MAXN 50000
#define MAXE 800000
#define K_DIM 128

// ---------------- scratch (__device__ globals; no allocs allowed) ----------------
__device__ float  g_dinv[MAXN];
__device__ int    g_deg[MAXN];
__device__ int    g_rowptr[MAXN + 1];
__device__ int    g_cursor[MAXN];
__device__ int    g_bsum[256];
__device__ int    g_boff[256];
__device__ int    g_arrive;
__device__ int    g_flag;
__device__ float2 g_csr[MAXE];
__device__ uint16_t g_h1[(size_t)MAXN * 128];   // fp16 gather buffer (layer 1)
__device__ float    g_buf1[(size_t)MAXN * 128];
__device__ uint16_t g_h2[(size_t)MAXN * 64];    // fp16 gather buffer (layer 2)
// bf16 split weights, plain row-major [k][n]
__device__ uint16_t g_w1h[128 * 128], g_w1l[128 * 128];
__device__ uint16_t g_w2h[128 * 64],  g_w2l[128 * 64];

// ---------------- packed f32x2 helpers (agg path) ----------------
__device__ __forceinline__ unsigned long long packdup(float x) {
    unsigned long long r;
    asm("mov.b64 %0, {%1, %1};" : "=l"(r) : "f"(x));
    return r;
}
__device__ __forceinline__ unsigned long long pack2(float x, float y) {
    unsigned long long r;
    asm("mov.b64 %0, {%1, %2};" : "=l"(r) : "f"(x), "f"(y));
    return r;
}
__device__ __forceinline__ unsigned long long ffma2v(unsigned long long a,
                                                     unsigned long long b,
                                                     unsigned long long c) {
    unsigned long long d;
    asm("fma.rn.f32x2 %0, %1, %2, %3;" : "=l"(d) : "l"(a), "l"(b), "l"(c));
    return d;
}
__device__ __forceinline__ unsigned long long add2(unsigned long long a,
                                                   unsigned long long b) {
    unsigned long long d;
    asm("add.rn.f32x2 %0, %1, %2;" : "=l"(d) : "l"(a), "l"(b));
    return d;
}
// gather 4 fp16 -> two packed f32x2, fma into acc
__device__ __forceinline__ void fma_h4(unsigned long long& a0, unsigned long long& a1,
                                       uint2 v, unsigned long long nrm) {
    float2 f0 = __half22float2(*(__half2*)&v.x);
    float2 f1 = __half22float2(*(__half2*)&v.y);
    a0 = ffma2v(pack2(f0.x, f0.y), nrm, a0);
    a1 = ffma2v(pack2(f1.x, f1.y), nrm, a1);
}

// ---------------- mma / ldmatrix helpers (sm_80-era, valid at compute_103) ----------------
__device__ __forceinline__ uint32_t smem_u32(const void* p) {
    uint32_t a;
    asm("{ .reg .u64 t; cvta.to.shared.u64 t, %1; cvt.u32.u64 %0, t; }"
        : "=r"(a) : "l"(p));
    return a;
}
__device__ __forceinline__ void mma16816(float* d, const uint32_t* a, const uint32_t* b) {
    asm volatile(
        "mma.sync.aligned.m16n8k16.row.col.f32.bf16.bf16.f32 "
        "{%0,%1,%2,%3}, {%4,%5,%6,%7}, {%8,%9}, {%0,%1,%2,%3};"
        : "+f"(d[0]), "+f"(d[1]), "+f"(d[2]), "+f"(d[3])
        : "r"(a[0]), "r"(a[1]), "r"(a[2]), "r"(a[3]), "r"(b[0]), "r"(b[1]));
}
__device__ __forceinline__ void ldsm_x4(uint32_t* r, uint32_t addr) {
    asm volatile("ldmatrix.sync.aligned.m8n8.x4.shared.b16 {%0,%1,%2,%3}, [%4];"
                 : "=r"(r[0]), "=r"(r[1]), "=r"(r[2]), "=r"(r[3]) : "r"(addr));
}
__device__ __forceinline__ void ldsm_x4t(uint32_t* r, uint32_t addr) {
    asm volatile("ldmatrix.sync.aligned.m8n8.x4.trans.shared.b16 {%0,%1,%2,%3}, [%4];"
                 : "=r"(r[0]), "=r"(r[1]), "=r"(r[2]), "=r"(r[3]) : "r"(addr));
}
__device__ __forceinline__ void split_bf16(float x, uint16_t& hi, uint16_t& lo) {
    __nv_bfloat16 h = __float2bfloat16_rn(x);
    __nv_bfloat16 l = __float2bfloat16_rn(x - __bfloat162float(h));
    hi = __bfloat16_as_ushort(h);
    lo = __bfloat16_as_ushort(l);
}

// ---------------- weight split (once per call) ----------------
__global__ void k_convW_all(const float* __restrict__ W1, const float* __restrict__ W2) {
    int idx = blockIdx.x * blockDim.x + threadIdx.x;
    if (idx < 128 * 128) {
        uint16_t h, l;
        split_bf16(W1[idx], h, l);
        g_w1h[idx] = h; g_w1l[idx] = l;
    } else if (idx < 128 * 128 + 128 * 64) {
        int j = idx - 128 * 128;
        uint16_t h, l;
        split_bf16(W2[j], h, l);
        g_w2h[j] = h; g_w2l[j] = l;
    }
}

// ---------------- degree / CSR build ----------------
__global__ void k_zero_deg(int n) {
    int i = blockIdx.x * blockDim.x + threadIdx.x;
    if (i < n) g_deg[i] = 0;
    if (i == 0) { g_arrive = 0; g_flag = 0; }
}

__global__ void k_count_deg(const int* __restrict__ ei, int E) {
    int i = blockIdx.x * blockDim.x + threadIdx.x;
    if (i < E) atomicAdd(&g_deg[ei[E + i]], 1);
}

__global__ void __launch_bounds__(256) k_scan_all(int n, int nb) {
    __shared__ int s[256];
    __shared__ int s_go;
    int t = threadIdx.x, b = blockIdx.x;
    int i = b * 256 + t;
    int v = (i < n) ? g_deg[i] : 0;
    if (i < n) g_dinv[i] = rsqrtf((float)v + 1.0f);
    s[t] = v;
    __syncthreads();
#pragma unroll
    for (int off = 1; off < 256; off <<= 1) {
        int a = (t >= off) ? s[t - off] : 0;
        __syncthreads();
        s[t] += a;
        __syncthreads();
    }
    int incl = s[t];
    if (t == 255) {
        g_bsum[b] = incl;
        __threadfence();
        int tk = atomicAdd(&g_arrive, 1);
        s_go = (tk == nb - 1);
    }
    __syncthreads();
    if (s_go) {
        int bv2 = (t < nb) ? g_bsum[t] : 0;
        s[t] = bv2;
        __syncthreads();
#pragma unroll
        for (int off = 1; off < 256; off <<= 1) {
            int a = (t >= off) ? s[t - off] : 0;
            __syncthreads();
            s[t] += a;
            __syncthreads();
        }
        if (t < nb) g_boff[t] = s[t] - bv2;
        __threadfence();
        if (t == 0) atomicExch(&g_flag, 1);
    } else {
        if (t == 0) { while (atomicAdd(&g_flag, 0) == 0) { } }
        __syncthreads();
    }
    int boff = *((volatile int*)&g_boff[b]);
    if (i < n) {
        int r = incl - v + boff;
        g_rowptr[i] = r;
        g_cursor[i] = r;
        if (i == n - 1) g_rowptr[n] = r + v;
    }
}

__global__ void k_scatter(const int* __restrict__ ei, int E) {
    int e = blockIdx.x * blockDim.x + threadIdx.x;
    if (e < E) {
        int s = ei[e];
        int d = ei[E + e];
        int pos = atomicAdd(&g_cursor[d], 1);
        g_csr[pos] = make_float2(__int_as_float(s), g_dinv[s] * g_dinv[d]);
    }
}

// ---------------- tensor-core GEMM: Hfp16 = X @ W ; OUT = bias + H*dinv^2 ----------------
// 256 threads = 8 warps; block tile 128 rows; each warp: 16 rows x NCOL cols.
// 3xBF16 split (hi*hi + hi*lo + lo*hi), fp32 accumulate via mma.sync m16n8k16.
template <int NCOL, bool RELU>
__global__ void __launch_bounds__(256, 1) k_gemm_mma(
    const float* __restrict__ X, const float* __restrict__ bias,
    const float* __restrict__ dinv, uint16_t* __restrict__ H16,
    float* __restrict__ OUT, int nrows)
{
    constexpr int PX = 136;                        // X pitch (bf16); 272B = 17 chunks
    constexpr int PW = (NCOL == 128) ? 136 : 72;   // W pitch; 272B/144B, conflict-free
    constexpr int NT = NCOL / 8;                   // n-tiles per warp

    extern __shared__ uint16_t sm16[];
    uint16_t* sXh = sm16;
    uint16_t* sXl = sXh + 128 * PX;
    uint16_t* sWh = sXl + 128 * PX;
    uint16_t* sWl = sWh + 128 * PW;

    const int tid  = threadIdx.x;
    const int warp = tid >> 5;
    const int lane = tid & 31;
    const int row0 = blockIdx.x * 128;

    // stage W from pre-split global bf16 [128][NCOL] into padded smem
    {
        const uint4* gh = (const uint4*)((NCOL == 128) ? g_w1h : g_w2h);
        const uint4* gl = (const uint4*)((NCOL == 128) ? g_w1l : g_w2l);
        for (int i = tid; i < 128 * (NCOL / 8); i += 256) {
            int k = i / (NCOL / 8), c = i % (NCOL / 8);
            ((uint4*)(sWh + k * PW))[c] = gh[i];
            ((uint4*)(sWl + k * PW))[c] = gl[i];
        }
    }

    // stage X: thread handles row tid/2, 64-col half tid&1; split to bf16 hi/lo
    {
        int r = tid >> 1, half = tid & 1;
        int row = row0 + r;
        uint32_t* dh = (uint32_t*)(sXh + r * PX + half * 64);
        uint32_t* dl = (uint32_t*)(sXl + r * PX + half * 64);
        if (row < nrows) {
            const float4* xr = (const float4*)(X + (size_t)row * K_DIM) + half * 16;
#pragma unroll 4
            for (int c4 = 0; c4 < 16; c4++) {
                float4 v = xr[c4];
                if (RELU) {
                    v.x = fmaxf(v.x, 0.f); v.y = fmaxf(v.y, 0.f);
                    v.z = fmaxf(v.z, 0.f); v.w = fmaxf(v.w, 0.f);
                }
                uint16_t h0, l0, h1, l1, h2, l2, h3, l3;
                split_bf16(v.x, h0, l0); split_bf16(v.y, h1, l1);
                split_bf16(v.z, h2, l2); split_bf16(v.w, h3, l3);
                dh[2 * c4]     = (uint32_t)h0 | ((uint32_t)h1 << 16);
                dh[2 * c4 + 1] = (uint32_t)h2 | ((uint32_t)h3 << 16);
                dl[2 * c4]     = (uint32_t)l0 | ((uint32_t)l1 << 16);
                dl[2 * c4 + 1] = (uint32_t)l2 | ((uint32_t)l3 << 16);
            }
        } else {
#pragma unroll 4
            for (int c4 = 0; c4 < 16; c4++) {
                dh[2 * c4] = 0u; dh[2 * c4 + 1] = 0u;
                dl[2 * c4] = 0u; dl[2 * c4 + 1] = 0u;
            }
        }
    }
    __syncthreads();

    const uint32_t bXh = smem_u32(sXh), bXl = smem_u32(sXl);
    const uint32_t bWh = smem_u32(sWh), bWl = smem_u32(sWl);

    float acc[NT][4];
#pragma unroll
    for (int j = 0; j < NT; j++) {
        acc[j][0] = 0.f; acc[j][1] = 0.f; acc[j][2] = 0.f; acc[j][3] = 0.f;
    }

    const int mrow = warp * 16;
    const uint32_t aoff = ((uint32_t)(mrow + (lane & 15)) * PX + ((lane >> 4) << 3)) * 2;
    const uint32_t boff = ((uint32_t)(lane & 15) * PW + ((lane >> 4) << 3)) * 2;

#pragma unroll
    for (int kt = 0; kt < 8; kt++) {
        uint32_t ah[4], al[4];
        ldsm_x4(ah, bXh + aoff + kt * 32);              // +16 bf16 cols per kt
        ldsm_x4(al, bXl + aoff + kt * 32);
        uint32_t bk = kt * 16 * PW * 2;                 // +16 k-rows per kt
#pragma unroll
        for (int np = 0; np < NT / 2; np++) {
            uint32_t bh[4], bl[4];
            ldsm_x4t(bh, bWh + boff + bk + np * 32);    // 2 n-tiles per ldmatrix
            ldsm_x4t(bl, bWl + boff + bk + np * 32);
            mma16816(acc[2 * np],     ah, bh);
            mma16816(acc[2 * np + 1], ah, bh + 2);
            mma16816(acc[2 * np],     ah, bl);
            mma16816(acc[2 * np + 1], ah, bl + 2);
            mma16816(acc[2 * np],     al, bh);
            mma16816(acc[2 * np + 1], al, bh + 2);
        }
    }

    // epilogue: thread owns rows (mrow + lane/4) and +8, col pairs (lane%4)*2 per ntile
    {
        int r0g = row0 + mrow + (lane >> 2);
        int r1g = r0g + 8;
        float d20 = 0.f, d21 = 0.f;
        if (r0g < nrows) { float di = dinv[r0g]; d20 = di * di; }
        if (r1g < nrows) { float di = dinv[r1g]; d21 = di * di; }
#pragma unroll
        for (int j = 0; j < NT; j++) {
            int col = j * 8 + (lane & 3) * 2;
            float2 bb = *(const float2*)(bias + col);
            if (r0g < nrows) {
                __half2 hh = __floats2half2_rn(acc[j][0], acc[j][1]);
                *(uint32_t*)(H16 + (size_t)r0g * NCOL + col) = *(uint32_t*)&hh;
                *(float2*)(OUT + (size_t)r0g * NCOL + col) =
                    make_float2(fmaf(acc[j][0], d20, bb.x), fmaf(acc[j][1], d20, bb.y));
            }
            if (r1g < nrows) {
                __half2 hh = __floats2half2_rn(acc[j][2], acc[j][3]);
                *(uint32_t*)(H16 + (size_t)r1g * NCOL + col) = *(uint32_t*)&hh;
                *(float2*)(OUT + (size_t)r1g * NCOL + col) =
                    make_float2(fmaf(acc[j][2], d21, bb.x), fmaf(acc[j][3], d21, bb.y));
            }
        }
    }
}

// ---------------- CSR aggregation: OUT[n] += sum_{e in row n} fp16(H[src_e]) * nrm_e ----------------
__global__ void __launch_bounds__(256) k_agg128(
    const uint16_t* __restrict__ H16, float* __restrict__ OUT, int N)
{
    int gw   = (blockIdx.x * 256 + threadIdx.x) >> 5;
    int lane = threadIdx.x & 31;
    if (gw >= N) return;
    int beg = g_rowptr[gw], end = g_rowptr[gw + 1];
    if (beg == end) return;

    const uint16_t* Hl = H16 + lane * 4;
    unsigned long long a0 = 0ull, a1 = 0ull;
    int j = beg;
    for (; j + 2 <= end; j += 2) {
        float2 e0 = g_csr[j];
        float2 e1 = g_csr[j + 1];
        uint2 v0 = *(const uint2*)(Hl + (size_t)__float_as_int(e0.x) * 128);
        uint2 v1 = *(const uint2*)(Hl + (size_t)__float_as_int(e1.x) * 128);
        fma_h4(a0, a1, v0, packdup(e0.y));
        fma_h4(a0, a1, v1, packdup(e1.y));
    }
    if (j < end) {
        float2 e0 = g_csr[j];
        uint2 v0 = *(const uint2*)(Hl + (size_t)__float_as_int(e0.x) * 128);
        fma_h4(a0, a1, v0, packdup(e0.y));
    }
    ulonglong2* op = (ulonglong2*)(OUT + (size_t)gw * 128 + lane * 4);
    ulonglong2 ob = *op;
    ob.x = add2(ob.x, a0);
    ob.y = add2(ob.y, a1);
    *op = ob;
}

__global__ void __launch_bounds__(256) k_agg64(
    const uint16_t* __restrict__ H16, float* __restrict__ OUT, int N)
{
    int idx  = blockIdx.x * 256 + threadIdx.x;
    int node = idx >> 4;
    int lane = idx & 15;
    if (node >= N) return;
    int beg = g_rowptr[node], end = g_rowptr[node + 1];
    if (beg == end) return;

    const uint16_t* Hl = H16 + lane * 4;
    unsigned long long a0 = 0ull, a1 = 0ull;
    int j = beg;
    for (; j + 2 <= end; j += 2) {
        float2 e0 = g_csr[j];
        float2 e1 = g_csr[j + 1];
        uint2 v0 = *(const uint2*)(Hl + (size_t)__float_as_int(e0.x) * 64);
        uint2 v1 = *(const uint2*)(Hl + (size_t)__float_as_int(e1.x) * 64);
        fma_h4(a0, a1, v0, packdup(e0.y));
        fma_h4(a0, a1, v1, packdup(e1.y));
    }
    if (j < end) {
        float2 e0 = g_csr[j];
        uint2 v0 = *(const uint2*)(Hl + (size_t)__float_as_int(e0.x) * 64);
        fma_h4(a0, a1, v0, packdup(e0.y));
    }
    ulonglong2* op = (ulonglong2*)(OUT + (size_t)node * 64 + lane * 4);
    ulonglong2 ob = *op;
    ob.x = add2(ob.x, a0);
    ob.y = add2(ob.y, a1);
    *op = ob;
}

// ---------------- launch ----------------
extern "C" void kernel_launch(void* const* d_in, const int* in_sizes, int n_in,
                              void* d_out, int out_size)
{
    const float* x  = (const float*)d_in[0];
    const int*   ei = (const int*)d_in[1];
    const float* W1 = (const float*)d_in[2];
    const float* b1 = (const float*)d_in[3];
    const float* W2 = (const float*)d_in[4];
    const float* b2 = (const float*)d_in[5];
    float*       out = (float*)d_out;

    const int N = in_sizes[0] / 128;   // 50000
    const int E = in_sizes[1] / 2;     // 800000

    float* dinv;   cudaGetSymbolAddress((void**)&dinv, g_dinv);
    uint16_t* h1;  cudaGetSymbolAddress((void**)&h1,   g_h1);
    float* buf1;   cudaGetSymbolAddress((void**)&buf1, g_buf1);
    uint16_t* h2;  cudaGetSymbolAddress((void**)&h2,   g_h2);

    const int SM1 = (2 * 128 * 136 + 2 * 128 * 136) * 2;  // 139264
    const int SM2 = (2 * 128 * 136 + 2 * 128 * 72) * 2;   // 106496
    cudaFuncSetAttribute((const void*)k_gemm_mma<128, false>,
                         cudaFuncAttributeMaxDynamicSharedMemorySize, SM1);
    cudaFuncSetAttribute((const void*)k_gemm_mma<64, true>,
                         cudaFuncAttributeMaxDynamicSharedMemorySize, SM2);

    const int nblkN = (N + 255) / 256;
    const int nblkE = (E + 255) / 256;

    // weight bf16 split (once per call)
    k_convW_all<<<(128 * 128 + 128 * 64 + 255) / 256, 256>>>(W1, W2);

    // CSR build
    k_zero_deg<<<nblkN, 256>>>(N);
    k_count_deg<<<nblkE, 256>>>(ei, E);
    k_scan_all<<<nblkN, 256>>>(N, nblkN);
    k_scatter<<<nblkE, 256>>>(ei, E);

    // layer 1: h1 = fp16(x@W1) ; buf1 = b1 + (x@W1)*dinv^2 (self-loop fused, fp32)
    int gblocks = (N + 127) / 128;   // 391
    k_gemm_mma<128, false><<<gblocks, 256, SM1>>>(x, b1, dinv, h1, buf1, N);
    k_agg128<<<(N * 32 + 255) / 256, 256>>>(h1, buf1, N);

    // layer 2: h2 = fp16(relu(buf1)@W2) ; out = b2 + (relu(buf1)@W2)*dinv^2
    k_gemm_mma<64, true><<<gblocks, 256, SM2>>>(buf1, b2, dinv, h2, out, N);
    k_agg64<<<(N * 16 + 255) / 256, 256>>>(h2, out, N);
}